// round 1
// baseline (speedup 1.0000x reference)
#include <cuda_runtime.h>
#include <cuda_bf16.h>
#include <math.h>

// Problem constants
#define Bq 2
#define Sq 2048
#define Dq 2048
#define Hq 8
#define KVq 2
#define HDq 256
#define WINDOWq 512
#define EPSq 1e-6f

#define BS_TOT (Bq * Sq)            // 4096

// Scratch (device globals; no allocation allowed)
__device__ float g_qraw[BS_TOT * Hq * HDq];    // [b*s, h*256]
__device__ float g_kraw[BS_TOT * KVq * HDq];
__device__ float g_vraw[BS_TOT * KVq * HDq];
__device__ float g_q[BS_TOT * Hq * HDq];       // [b, h, s, 256]
__device__ float g_k[BS_TOT * KVq * HDq];      // [b, kv, s, 256]
__device__ float g_v[BS_TOT * KVq * HDq];      // [b, kv, s, 256]
__device__ float g_attn[BS_TOT * Hq * HDq];    // [b, s, h, 256]

// ---------------------------------------------------------------------------
// SGEMM: C[M,N] = A[M,K] @ B[K,N], all row-major, fp32.
// BM=128, BN=128, BK=8, 256 threads, 8x8 per thread.
// M % 128 == 0, N % 128 == 0, K % 8 == 0 (true for all our shapes).
// ---------------------------------------------------------------------------
__global__ __launch_bounds__(256) void sgemm128(int M, int N, int K,
                                                const float* __restrict__ A,
                                                const float* __restrict__ B,
                                                float* __restrict__ C) {
    constexpr int BM = 128, BN = 128, BK = 8, TM = 8, TN = 8;
    __shared__ float As[BK][BM];
    __shared__ float Bs[BK][BN];

    const int tid = threadIdx.x;
    const int brow = blockIdx.y;
    const int bcol = blockIdx.x;

    const int trow = tid / 16;          // 0..15
    const int tcol = tid % 16;          // 0..15

    // A tile load: 128x8 floats = 256 float4 (transposed into As[k][m])
    const int a_r = tid >> 1;           // 0..127
    const int a_c = (tid & 1) << 2;     // 0 or 4
    // B tile load: 8x128 floats = 256 float4
    const int b_r = tid >> 5;           // 0..7
    const int b_c = (tid & 31) << 2;    // 0..124

    const float* Ab = A + (size_t)brow * BM * K;
    const float* Bb = B + (size_t)bcol * BN;

    float acc[TM][TN];
#pragma unroll
    for (int m = 0; m < TM; m++)
#pragma unroll
        for (int n = 0; n < TN; n++) acc[m][n] = 0.f;

    for (int k0 = 0; k0 < K; k0 += BK) {
        float4 av = *(const float4*)(Ab + (size_t)a_r * K + k0 + a_c);
        As[a_c + 0][a_r] = av.x;
        As[a_c + 1][a_r] = av.y;
        As[a_c + 2][a_r] = av.z;
        As[a_c + 3][a_r] = av.w;
        float4 bv = *(const float4*)(Bb + (size_t)(k0 + b_r) * N + b_c);
        *(float4*)&Bs[b_r][b_c] = bv;
        __syncthreads();

#pragma unroll
        for (int kk = 0; kk < BK; kk++) {
            float ra[TM], rb[TN];
#pragma unroll
            for (int m = 0; m < TM; m += 4) {
                float4 t = *(const float4*)&As[kk][trow * TM + m];
                ra[m] = t.x; ra[m + 1] = t.y; ra[m + 2] = t.z; ra[m + 3] = t.w;
            }
#pragma unroll
            for (int n = 0; n < TN; n += 4) {
                float4 t = *(const float4*)&Bs[kk][tcol * TN + n];
                rb[n] = t.x; rb[n + 1] = t.y; rb[n + 2] = t.z; rb[n + 3] = t.w;
            }
#pragma unroll
            for (int m = 0; m < TM; m++)
#pragma unroll
                for (int n = 0; n < TN; n++) acc[m][n] = fmaf(ra[m], rb[n], acc[m][n]);
        }
        __syncthreads();
    }

    float* Cb = C + (size_t)(brow * BM) * N + bcol * BN;
#pragma unroll
    for (int m = 0; m < TM; m++) {
        int r = trow * TM + m;
#pragma unroll
        for (int n = 0; n < TN; n += 4) {
            float4 v;
            v.x = acc[m][n]; v.y = acc[m][n + 1]; v.z = acc[m][n + 2]; v.w = acc[m][n + 3];
            *(float4*)(Cb + (size_t)r * N + tcol * TN + n) = v;
        }
    }
}

// ---------------------------------------------------------------------------
// RMSNorm + RoPE for Q/K.  One block per (b*s, head) row of 256.
// raw: [B*S, NH*256]; out: [B, NH, S, 256]; cos/sin: [B, S, 256]
// ---------------------------------------------------------------------------
__global__ __launch_bounds__(256) void norm_rope_kernel(const float* __restrict__ raw,
                                                        const float* __restrict__ cosb,
                                                        const float* __restrict__ sinb,
                                                        const float* __restrict__ w,
                                                        float* __restrict__ out,
                                                        int NH) {
    const int bs = blockIdx.x;        // 0..B*S-1
    const int h  = blockIdx.y;
    const int t  = threadIdx.x;       // 0..255
    const int b  = bs / Sq;
    const int s  = bs % Sq;

    float x = raw[(size_t)bs * (NH * HDq) + h * HDq + t];

    __shared__ float red[8];
    float v = x * x;
#pragma unroll
    for (int o = 16; o; o >>= 1) v += __shfl_xor_sync(0xFFFFFFFFu, v, o);
    if ((t & 31) == 0) red[t >> 5] = v;
    __syncthreads();
    float tot = 0.f;
#pragma unroll
    for (int i = 0; i < 8; i++) tot += red[i];
    float inv = rsqrtf(tot * (1.f / HDq) + EPSq);
    float y = x * inv * w[t];

    __shared__ float sy[HDq];
    sy[t] = y;
    __syncthreads();
    float rot = (t < 128) ? -sy[t + 128] : sy[t - 128];
    float c = cosb[(size_t)bs * HDq + t];
    float sn = sinb[(size_t)bs * HDq + t];
    float o = y * c + rot * sn;

    out[(((size_t)b * NH + h) * Sq + s) * HDq + t] = o;
}

// RMSNorm only (weight = 1.0) for V.  out: [B, KV, S, 256]
__global__ __launch_bounds__(256) void norm_v_kernel(const float* __restrict__ raw,
                                                     float* __restrict__ out) {
    const int bs = blockIdx.x;
    const int h  = blockIdx.y;        // 0..KV-1
    const int t  = threadIdx.x;
    const int b  = bs / Sq;
    const int s  = bs % Sq;

    float x = raw[(size_t)bs * (KVq * HDq) + h * HDq + t];

    __shared__ float red[8];
    float v = x * x;
#pragma unroll
    for (int o = 16; o; o >>= 1) v += __shfl_xor_sync(0xFFFFFFFFu, v, o);
    if ((t & 31) == 0) red[t >> 5] = v;
    __syncthreads();
    float tot = 0.f;
#pragma unroll
    for (int i = 0; i < 8; i++) tot += red[i];
    float inv = rsqrtf(tot * (1.f / HDq) + EPSq);

    out[(((size_t)b * KVq + h) * Sq + s) * HDq + t] = x * inv;
}

// ---------------------------------------------------------------------------
// Sliding-window attention.  One warp per query; 8 queries / block.
// Q: [B,H,S,256]  K,V: [B,KV,S,256]  O: [B,S,H,256]
// No softmax scale (reference has none). Mask == sliding window, applied by
// restricting the key range (exact: masked logits are -1e9 -> exp == 0).
// ---------------------------------------------------------------------------
#define ATK 16
__global__ __launch_bounds__(256) void attn_kernel(const float* __restrict__ Q,
                                                   const float* __restrict__ Kt,
                                                   const float* __restrict__ Vt,
                                                   float* __restrict__ O) {
    __shared__ float Ks[ATK][HDq];
    __shared__ float Vs[ATK][HDq];

    const int bh = blockIdx.y;              // 0..B*H-1
    const int b = bh / Hq, h = bh % Hq;
    const int hk = h / (Hq / KVq);
    const int qbase = blockIdx.x * 8;
    const int warp = threadIdx.x >> 5;
    const int lane = threadIdx.x & 31;
    const int q = qbase + warp;

    // Q fragment: lane holds elements {lane, lane+32, ..., lane+224}
    const float* qp = Q + (((size_t)b * Hq + h) * Sq + q) * HDq;
    float qf[8];
#pragma unroll
    for (int e = 0; e < 8; e++) qf[e] = qp[lane + 32 * e];

    const float* Kb = Kt + ((size_t)b * KVq + hk) * Sq * HDq;
    const float* Vb = Vt + ((size_t)b * KVq + hk) * Sq * HDq;

    const int lo = max(0, qbase - (WINDOWq - 1));
    const int hi = qbase + 7;               // inclusive

    float m = -1e30f, l = 0.f;
    float o[8];
#pragma unroll
    for (int e = 0; e < 8; e++) o[e] = 0.f;

    for (int t0 = lo; t0 <= hi; t0 += ATK) {
        const int nrows = min(ATK, hi - t0 + 1);
        // Cooperative tile load: nrows*64 float4 per array.
        for (int i = threadIdx.x; i < nrows * 64; i += 256) {
            int r = i >> 6;
            int cc = (i & 63) << 2;
            *(float4*)&Ks[r][cc] = *(const float4*)(Kb + (size_t)(t0 + r) * HDq + cc);
            *(float4*)&Vs[r][cc] = *(const float4*)(Vb + (size_t)(t0 + r) * HDq + cc);
        }
        __syncthreads();

        const int jmin = max(0, (q - (WINDOWq - 1)) - t0);
        const int jmax = min(nrows, q - t0 + 1);
        for (int j = jmin; j < jmax; j++) {
            float s = 0.f;
#pragma unroll
            for (int e = 0; e < 8; e++) s = fmaf(qf[e], Ks[j][lane + 32 * e], s);
#pragma unroll
            for (int off = 16; off; off >>= 1) s += __shfl_xor_sync(0xFFFFFFFFu, s, off);

            float mn = fmaxf(m, s);
            float scale = __expf(m - mn);
            float p = __expf(s - mn);
            l = l * scale + p;
            m = mn;
#pragma unroll
            for (int e = 0; e < 8; e++)
                o[e] = fmaf(p, Vs[j][lane + 32 * e], o[e] * scale);
        }
        __syncthreads();
    }

    const float invl = 1.f / l;
    float* op = O + (((size_t)b * Sq + q) * Hq + h) * HDq;
#pragma unroll
    for (int e = 0; e < 8; e++) op[lane + 32 * e] = o[e] * invl;
}

// ---------------------------------------------------------------------------
extern "C" void kernel_launch(void* const* d_in, const int* in_sizes, int n_in,
                              void* d_out, int out_size) {
    (void)in_sizes; (void)n_in; (void)out_size;
    const float* hidden = (const float*)d_in[0];   // [B,S,D]
    const float* cosb   = (const float*)d_in[1];   // [B,S,256]
    const float* sinb   = (const float*)d_in[2];   // [B,S,256]
    // d_in[3] = attention_mask: replaced exactly by the sliding-window range.
    const float* wq     = (const float*)d_in[4];   // [D, H*256]
    const float* wk     = (const float*)d_in[5];   // [D, KV*256]
    const float* wv     = (const float*)d_in[6];   // [D, KV*256]
    const float* wo     = (const float*)d_in[7];   // [H*256, D]
    const float* qnw    = (const float*)d_in[8];   // [256]
    const float* knw    = (const float*)d_in[9];   // [256]
    float* out = (float*)d_out;                    // [B,S,D]

    float *qraw, *kraw, *vraw, *qn, *kn, *vn, *attn;
    cudaGetSymbolAddress((void**)&qraw, g_qraw);
    cudaGetSymbolAddress((void**)&kraw, g_kraw);
    cudaGetSymbolAddress((void**)&vraw, g_vraw);
    cudaGetSymbolAddress((void**)&qn,   g_q);
    cudaGetSymbolAddress((void**)&kn,   g_k);
    cudaGetSymbolAddress((void**)&vn,   g_v);
    cudaGetSymbolAddress((void**)&attn, g_attn);

    // 1) QKV projections (fp32 SGEMM)
    {
        dim3 gq(Hq * HDq / 128, BS_TOT / 128);     // 16 x 32
        sgemm128<<<gq, 256>>>(BS_TOT, Hq * HDq, Dq, hidden, wq, qraw);
        dim3 gk(KVq * HDq / 128, BS_TOT / 128);    // 4 x 32
        sgemm128<<<gk, 256>>>(BS_TOT, KVq * HDq, Dq, hidden, wk, kraw);
        sgemm128<<<gk, 256>>>(BS_TOT, KVq * HDq, Dq, hidden, wv, vraw);
    }

    // 2) RMSNorm + RoPE (Q, K), RMSNorm (V); transpose to [b, h, s, hd]
    {
        dim3 gq(BS_TOT, Hq);
        norm_rope_kernel<<<gq, 256>>>(qraw, cosb, sinb, qnw, qn, Hq);
        dim3 gk(BS_TOT, KVq);
        norm_rope_kernel<<<gk, 256>>>(kraw, cosb, sinb, knw, kn, KVq);
        norm_v_kernel<<<gk, 256>>>(vraw, vn);
    }

    // 3) Sliding-window attention -> [b, s, h, hd]
    {
        dim3 ga(Sq / 8, Bq * Hq);                  // 256 x 16
        attn_kernel<<<ga, 256>>>(qn, kn, vn, attn);
    }

    // 4) Output projection
    {
        dim3 go(Dq / 128, BS_TOT / 128);           // 16 x 32
        sgemm128<<<go, 256>>>(BS_TOT, Dq, Hq * HDq, attn, wo, out);
    }
}

// round 4
// speedup vs baseline: 1.2697x; 1.2697x over previous
#include <cuda_runtime.h>
#include <cuda_bf16.h>
#include <math.h>
#include <stdint.h>

// Problem constants
#define Bq 2
#define Sq 2048
#define Dq 2048
#define Hq 8
#define KVq 2
#define HDq 256
#define WINDOWq 512
#define EPSq 1e-6f

#define BS_TOT (Bq * Sq)            // 4096

// ---------------------------------------------------------------------------
// Scratch (device globals; no allocation allowed)
// ---------------------------------------------------------------------------
__device__ float g_wqT [Hq * HDq * Dq];        // wq^T  [N=2048, K=2048]
__device__ float g_wkT [KVq * HDq * Dq];       // wk^T  [512, 2048]
__device__ float g_wvT [KVq * HDq * Dq];       // wv^T
__device__ float g_woT [Dq * Hq * HDq];        // wo^T  [2048, 2048]
__device__ float g_qraw[BS_TOT * Hq * HDq];    // [b*s, h*256]
__device__ float g_kraw[BS_TOT * KVq * HDq];
__device__ float g_vraw[BS_TOT * KVq * HDq];
__device__ float g_q[BS_TOT * Hq * HDq];       // [b, h, s, 256]
__device__ float g_k[BS_TOT * KVq * HDq];      // [b, kv, s, 256]
__device__ float g_v[BS_TOT * KVq * HDq];      // [b, kv, s, 256]
__device__ float g_attn[BS_TOT * Hq * HDq];    // [b, s, h, 256]

// ---------------------------------------------------------------------------
// Helpers
// ---------------------------------------------------------------------------
__device__ __forceinline__ float rna_tf32(float x) {
    float r;
    asm("cvt.rna.tf32.f32 %0, %1;" : "=f"(r) : "f"(x));
    return r;
}

__device__ __forceinline__ uint32_t smem_u32(const void* p) {
    uint32_t a;
    asm("{ .reg .u64 t; cvta.to.shared.u64 t, %1; cvt.u32.u64 %0, t; }" : "=r"(a) : "l"(p));
    return a;
}

__device__ __forceinline__ void cp_async16(uint32_t dst, const void* src) {
    asm volatile("cp.async.cg.shared.global [%0], [%1], 16;\n" :: "r"(dst), "l"(src));
}

// m16n8k8 tf32 mma (sm_80+ PTX; no 'a' arch feature needed)
__device__ __forceinline__ void mma_tf32(float c[4], const uint32_t a[4], const uint32_t b[2]) {
    asm volatile(
        "mma.sync.aligned.m16n8k8.row.col.f32.tf32.tf32.f32 "
        "{%0,%1,%2,%3}, {%4,%5,%6,%7}, {%8,%9}, {%0,%1,%2,%3};"
        : "+f"(c[0]), "+f"(c[1]), "+f"(c[2]), "+f"(c[3])
        : "r"(a[0]), "r"(a[1]), "r"(a[2]), "r"(a[3]), "r"(b[0]), "r"(b[1]));
}

// ---------------------------------------------------------------------------
// 3xTF32 split-precision tensor-core GEMM:
//   C[M,N] = A[M,K] @ Bt[N,K]^T   (A, Bt raw fp32; Bt K-major)
// Each input split a = a_hi + a_lo (both tf32-exact); accumulate
//   c += a_lo*b_hi + a_hi*b_lo + a_hi*b_hi   (fp32 accumulators)
// -> ~2^-22 effective input precision, ~1e-5 output rel err.
// CTA tile 128x128, BK=16, 256 threads (8 warps), warp tile 64x32.
// 3-stage cp.async pipeline. Smem rows padded to 20 floats (conflict-free).
// ---------------------------------------------------------------------------
#define GSTAGES 3
#define GROWPAD 20                               // 16 + 4 floats
#define GTILE_BYTES (128 * GROWPAD * 4)          // 10240
#define GSTAGE_BYTES (2 * GTILE_BYTES)           // 20480
#define GSMEM_REQ (GSTAGES * GSTAGE_BYTES)       // 61440

__global__ __launch_bounds__(256) void gemm_tc(int M, int N, int K,
                                               const float* __restrict__ A,
                                               const float* __restrict__ Bt,
                                               float* __restrict__ C) {
    extern __shared__ char smem_raw[];
    float* smem_f = (float*)smem_raw;
    const uint32_t smem_base = smem_u32(smem_raw);

    const int tid = threadIdx.x;
    const int wid = tid >> 5;
    const int lane = tid & 31;
    const int g = lane >> 2;          // groupID 0..7
    const int t = lane & 3;           // thread-in-group 0..3

    const int bm = blockIdx.y;
    const int bn = blockIdx.x;
    const int warp_m = (wid & 1) * 64;    // 2 warps over M
    const int warp_n = (wid >> 1) * 32;   // 4 warps over N

    const float* Ab = A + (size_t)bm * 128 * K;
    const float* Bb = Bt + (size_t)bn * 128 * K;
    const int niters = K / 16;

    // cp.async load indices: tile = 128 rows x 4 float4; 512 float4, 2/thread
    const int l_row0 = tid >> 1;                // rows 0..127
    const int l_c40  = (tid & 1) << 1;          // float4 col 0 or 2 -> +1 for j=1

    float c[4][4][4];
#pragma unroll
    for (int mt = 0; mt < 4; mt++)
#pragma unroll
        for (int nt = 0; nt < 4; nt++)
#pragma unroll
            for (int i = 0; i < 4; i++) c[mt][nt][i] = 0.f;

    // Prologue: issue loads for chunks 0, 1
#pragma unroll
    for (int st = 0; st < 2; st++) {
        const uint32_t a_s = smem_base + st * GSTAGE_BYTES;
        const uint32_t b_s = a_s + GTILE_BYTES;
        const float* Ak = Ab + st * 16;
        const float* Bk = Bb + st * 16;
#pragma unroll
        for (int j = 0; j < 2; j++) {
            int row = l_row0, c4 = l_c40 + j;
            cp_async16(a_s + (row * GROWPAD + c4 * 4) * 4, Ak + (size_t)row * K + c4 * 4);
            cp_async16(b_s + (row * GROWPAD + c4 * 4) * 4, Bk + (size_t)row * K + c4 * 4);
        }
        asm volatile("cp.async.commit_group;" ::: "memory");
    }

    for (int it = 0; it < niters; it++) {
        // Issue load for chunk it+2 into stage (it+2)%3
        if (it + 2 < niters) {
            const int rs = (it + 2) % GSTAGES;
            const uint32_t a_s = smem_base + rs * GSTAGE_BYTES;
            const uint32_t b_s = a_s + GTILE_BYTES;
            const float* Ak = Ab + (it + 2) * 16;
            const float* Bk = Bb + (it + 2) * 16;
#pragma unroll
            for (int j = 0; j < 2; j++) {
                int row = l_row0, c4 = l_c40 + j;
                cp_async16(a_s + (row * GROWPAD + c4 * 4) * 4, Ak + (size_t)row * K + c4 * 4);
                cp_async16(b_s + (row * GROWPAD + c4 * 4) * 4, Bk + (size_t)row * K + c4 * 4);
            }
            asm volatile("cp.async.commit_group;" ::: "memory");
            asm volatile("cp.async.wait_group 2;" ::: "memory");
        } else if (it + 1 < niters) {
            asm volatile("cp.async.wait_group 1;" ::: "memory");
        } else {
            asm volatile("cp.async.wait_group 0;" ::: "memory");
        }
        __syncthreads();

        const int s = it % GSTAGES;
        const float* As = smem_f + s * (GSTAGE_BYTES / 4);
        const float* Bs = As + (GTILE_BYTES / 4);

#pragma unroll
        for (int ks = 0; ks < 16; ks += 8) {
            uint32_t ahi[4][4], alo[4][4], bhi[4][2], blo[4][2];
#pragma unroll
            for (int mt = 0; mt < 4; mt++) {
                const int m0 = warp_m + mt * 16;
                float f0 = As[(m0 + g)     * GROWPAD + ks + t];
                float f1 = As[(m0 + 8 + g) * GROWPAD + ks + t];
                float f2 = As[(m0 + g)     * GROWPAD + ks + t + 4];
                float f3 = As[(m0 + 8 + g) * GROWPAD + ks + t + 4];
                float h0 = rna_tf32(f0), h1 = rna_tf32(f1);
                float h2 = rna_tf32(f2), h3 = rna_tf32(f3);
                ahi[mt][0] = __float_as_uint(h0); alo[mt][0] = __float_as_uint(rna_tf32(f0 - h0));
                ahi[mt][1] = __float_as_uint(h1); alo[mt][1] = __float_as_uint(rna_tf32(f1 - h1));
                ahi[mt][2] = __float_as_uint(h2); alo[mt][2] = __float_as_uint(rna_tf32(f2 - h2));
                ahi[mt][3] = __float_as_uint(h3); alo[mt][3] = __float_as_uint(rna_tf32(f3 - h3));
            }
#pragma unroll
            for (int nt = 0; nt < 4; nt++) {
                const int n0 = warp_n + nt * 8;
                float f0 = Bs[(n0 + g) * GROWPAD + ks + t];
                float f1 = Bs[(n0 + g) * GROWPAD + ks + t + 4];
                float h0 = rna_tf32(f0), h1 = rna_tf32(f1);
                bhi[nt][0] = __float_as_uint(h0); blo[nt][0] = __float_as_uint(rna_tf32(f0 - h0));
                bhi[nt][1] = __float_as_uint(h1); blo[nt][1] = __float_as_uint(rna_tf32(f1 - h1));
            }
#pragma unroll
            for (int mt = 0; mt < 4; mt++)
#pragma unroll
                for (int nt = 0; nt < 4; nt++) {
                    mma_tf32(c[mt][nt], alo[mt], bhi[nt]);
                    mma_tf32(c[mt][nt], ahi[mt], blo[nt]);
                    mma_tf32(c[mt][nt], ahi[mt], bhi[nt]);
                }
        }
        __syncthreads();
    }

    // Epilogue
    float* Cb = C + (size_t)(bm * 128) * N + bn * 128;
#pragma unroll
    for (int mt = 0; mt < 4; mt++) {
#pragma unroll
        for (int nt = 0; nt < 4; nt++) {
            const int r0 = warp_m + mt * 16 + g;
            const int c0 = warp_n + nt * 8 + t * 2;
            float2 v0 = make_float2(c[mt][nt][0], c[mt][nt][1]);
            float2 v1 = make_float2(c[mt][nt][2], c[mt][nt][3]);
            *(float2*)(Cb + (size_t)r0 * N + c0) = v0;
            *(float2*)(Cb + (size_t)(r0 + 8) * N + c0) = v1;
        }
    }
}

// Transpose:  w[K,N] -> wt[N,K]
__global__ __launch_bounds__(256) void transp_kernel(const float* __restrict__ w,
                                                     float* __restrict__ wt,
                                                     int Kd, int Nd) {
    __shared__ float tile[32][33];
    const int n0 = blockIdx.x * 32, k0 = blockIdx.y * 32;
    const int tx = threadIdx.x, ty = threadIdx.y;
#pragma unroll
    for (int j = ty; j < 32; j += 8)
        tile[j][tx] = w[(size_t)(k0 + j) * Nd + n0 + tx];
    __syncthreads();
#pragma unroll
    for (int j = ty; j < 32; j += 8)
        wt[(size_t)(n0 + j) * Kd + k0 + tx] = tile[tx][j];
}

// ---------------------------------------------------------------------------
// RMSNorm + RoPE for Q/K.  One block per (b*s, head) row of 256.
// ---------------------------------------------------------------------------
__global__ __launch_bounds__(256) void norm_rope_kernel(const float* __restrict__ raw,
                                                        const float* __restrict__ cosb,
                                                        const float* __restrict__ sinb,
                                                        const float* __restrict__ w,
                                                        float* __restrict__ out,
                                                        int NH) {
    const int bs = blockIdx.x;
    const int h  = blockIdx.y;
    const int t  = threadIdx.x;
    const int b  = bs / Sq;
    const int s  = bs % Sq;

    float x = raw[(size_t)bs * (NH * HDq) + h * HDq + t];

    __shared__ float red[8];
    float v = x * x;
#pragma unroll
    for (int o = 16; o; o >>= 1) v += __shfl_xor_sync(0xFFFFFFFFu, v, o);
    if ((t & 31) == 0) red[t >> 5] = v;
    __syncthreads();
    float tot = 0.f;
#pragma unroll
    for (int i = 0; i < 8; i++) tot += red[i];
    float inv = rsqrtf(tot * (1.f / HDq) + EPSq);
    float y = x * inv * w[t];

    __shared__ float sy[HDq];
    sy[t] = y;
    __syncthreads();
    float rot = (t < 128) ? -sy[t + 128] : sy[t - 128];
    float c = cosb[(size_t)bs * HDq + t];
    float sn = sinb[(size_t)bs * HDq + t];
    float o = y * c + rot * sn;

    out[(((size_t)b * NH + h) * Sq + s) * HDq + t] = o;
}

__global__ __launch_bounds__(256) void norm_v_kernel(const float* __restrict__ raw,
                                                     float* __restrict__ out) {
    const int bs = blockIdx.x;
    const int h  = blockIdx.y;
    const int t  = threadIdx.x;
    const int b  = bs / Sq;
    const int s  = bs % Sq;

    float x = raw[(size_t)bs * (KVq * HDq) + h * HDq + t];

    __shared__ float red[8];
    float v = x * x;
#pragma unroll
    for (int o = 16; o; o >>= 1) v += __shfl_xor_sync(0xFFFFFFFFu, v, o);
    if ((t & 31) == 0) red[t >> 5] = v;
    __syncthreads();
    float tot = 0.f;
#pragma unroll
    for (int i = 0; i < 8; i++) tot += red[i];
    float inv = rsqrtf(tot * (1.f / HDq) + EPSq);

    out[(((size_t)b * KVq + h) * Sq + s) * HDq + t] = x * inv;
}

// ---------------------------------------------------------------------------
// Sliding-window attention (fp32, warp-per-query).
// ---------------------------------------------------------------------------
#define ATK 16
__global__ __launch_bounds__(256) void attn_kernel(const float* __restrict__ Q,
                                                   const float* __restrict__ Kt,
                                                   const float* __restrict__ Vt,
                                                   float* __restrict__ O) {
    __shared__ float Ks[ATK][HDq];
    __shared__ float Vs[ATK][HDq];

    const int bh = blockIdx.y;
    const int b = bh / Hq, h = bh % Hq;
    const int hk = h / (Hq / KVq);
    const int qbase = blockIdx.x * 8;
    const int warp = threadIdx.x >> 5;
    const int lane = threadIdx.x & 31;
    const int q = qbase + warp;

    const float* qp = Q + (((size_t)b * Hq + h) * Sq + q) * HDq;
    float qf[8];
#pragma unroll
    for (int e = 0; e < 8; e++) qf[e] = qp[lane + 32 * e];

    const float* Kb = Kt + ((size_t)b * KVq + hk) * Sq * HDq;
    const float* Vb = Vt + ((size_t)b * KVq + hk) * Sq * HDq;

    const int lo = max(0, qbase - (WINDOWq - 1));
    const int hi = qbase + 7;

    float m = -1e30f, l = 0.f;
    float o[8];
#pragma unroll
    for (int e = 0; e < 8; e++) o[e] = 0.f;

    for (int t0 = lo; t0 <= hi; t0 += ATK) {
        const int nrows = min(ATK, hi - t0 + 1);
        for (int i = threadIdx.x; i < nrows * 64; i += 256) {
            int r = i >> 6;
            int cc = (i & 63) << 2;
            *(float4*)&Ks[r][cc] = *(const float4*)(Kb + (size_t)(t0 + r) * HDq + cc);
            *(float4*)&Vs[r][cc] = *(const float4*)(Vb + (size_t)(t0 + r) * HDq + cc);
        }
        __syncthreads();

        const int jmin = max(0, (q - (WINDOWq - 1)) - t0);
        const int jmax = min(nrows, q - t0 + 1);
        for (int j = jmin; j < jmax; j++) {
            float s = 0.f;
#pragma unroll
            for (int e = 0; e < 8; e++) s = fmaf(qf[e], Ks[j][lane + 32 * e], s);
#pragma unroll
            for (int off = 16; off; off >>= 1) s += __shfl_xor_sync(0xFFFFFFFFu, s, off);

            float mn = fmaxf(m, s);
            float scale = __expf(m - mn);
            float p = __expf(s - mn);
            l = l * scale + p;
            m = mn;
#pragma unroll
            for (int e = 0; e < 8; e++)
                o[e] = fmaf(p, Vs[j][lane + 32 * e], o[e] * scale);
        }
        __syncthreads();
    }

    const float invl = 1.f / l;
    float* op = O + (((size_t)b * Sq + q) * Hq + h) * HDq;
#pragma unroll
    for (int e = 0; e < 8; e++) op[lane + 32 * e] = o[e] * invl;
}

// ---------------------------------------------------------------------------
extern "C" void kernel_launch(void* const* d_in, const int* in_sizes, int n_in,
                              void* d_out, int out_size) {
    (void)in_sizes; (void)n_in; (void)out_size;
    const float* hidden = (const float*)d_in[0];
    const float* cosb   = (const float*)d_in[1];
    const float* sinb   = (const float*)d_in[2];
    // d_in[3] = attention_mask: replaced exactly by the sliding-window range.
    const float* wq     = (const float*)d_in[4];
    const float* wk     = (const float*)d_in[5];
    const float* wv     = (const float*)d_in[6];
    const float* wo     = (const float*)d_in[7];
    const float* qnw    = (const float*)d_in[8];
    const float* knw    = (const float*)d_in[9];
    float* out = (float*)d_out;

    float *wqT, *wkT, *wvT, *woT;
    float *qraw, *kraw, *vraw, *qn, *kn, *vn, *attn;
    cudaGetSymbolAddress((void**)&wqT,  g_wqT);
    cudaGetSymbolAddress((void**)&wkT,  g_wkT);
    cudaGetSymbolAddress((void**)&wvT,  g_wvT);
    cudaGetSymbolAddress((void**)&woT,  g_woT);
    cudaGetSymbolAddress((void**)&qraw, g_qraw);
    cudaGetSymbolAddress((void**)&kraw, g_kraw);
    cudaGetSymbolAddress((void**)&vraw, g_vraw);
    cudaGetSymbolAddress((void**)&qn,   g_q);
    cudaGetSymbolAddress((void**)&kn,   g_k);
    cudaGetSymbolAddress((void**)&vn,   g_v);
    cudaGetSymbolAddress((void**)&attn, g_attn);

    cudaFuncSetAttribute(gemm_tc, cudaFuncAttributeMaxDynamicSharedMemorySize, GSMEM_REQ);

    // 0) weight transposes (GEMM wants B as [N,K] K-major)
    {
        dim3 tb(32, 8);
        transp_kernel<<<dim3(Hq * HDq / 32,  Dq / 32), tb>>>(wq, wqT, Dq, Hq * HDq);
        transp_kernel<<<dim3(KVq * HDq / 32, Dq / 32), tb>>>(wk, wkT, Dq, KVq * HDq);
        transp_kernel<<<dim3(KVq * HDq / 32, Dq / 32), tb>>>(wv, wvT, Dq, KVq * HDq);
        transp_kernel<<<dim3(Dq / 32, Hq * HDq / 32),  tb>>>(wo, woT, Hq * HDq, Dq);
    }

    // 1) QKV projections (3xTF32 tensor cores, raw fp32 in)
    {
        gemm_tc<<<dim3(Hq * HDq / 128,  BS_TOT / 128), 256, GSMEM_REQ>>>(BS_TOT, Hq * HDq,  Dq, hidden, wqT, qraw);
        gemm_tc<<<dim3(KVq * HDq / 128, BS_TOT / 128), 256, GSMEM_REQ>>>(BS_TOT, KVq * HDq, Dq, hidden, wkT, kraw);
        gemm_tc<<<dim3(KVq * HDq / 128, BS_TOT / 128), 256, GSMEM_REQ>>>(BS_TOT, KVq * HDq, Dq, hidden, wvT, vraw);
    }

    // 2) RMSNorm + RoPE (Q, K), RMSNorm (V)
    {
        dim3 gq(BS_TOT, Hq);
        norm_rope_kernel<<<gq, 256>>>(qraw, cosb, sinb, qnw, qn, Hq);
        dim3 gk(BS_TOT, KVq);
        norm_rope_kernel<<<gk, 256>>>(kraw, cosb, sinb, knw, kn, KVq);
        norm_v_kernel<<<gk, 256>>>(vraw, vn);
    }

    // 3) Sliding-window attention -> [b, s, h, hd]
    {
        dim3 ga(Sq / 8, Bq * Hq);
        attn_kernel<<<ga, 256>>>(qn, kn, vn, attn);
    }

    // 4) Output projection (3xTF32 tensor cores)
    {
        gemm_tc<<<dim3(Dq / 128, BS_TOT / 128), 256, GSMEM_REQ>>>(BS_TOT, Dq, Hq * HDq, attn, woT, out);
    }
}